// round 1
// baseline (speedup 1.0000x reference)
#include <cuda_runtime.h>
#include <math.h>

// Problem constants
#define BB 256      // batch
#define TT 128      // time steps
#define EMBED 256
#define HIDDEN 512
#define VOCAB 1004
#define FC_IN 2048
#define GATES 2048  // 4*HIDDEN

// -------------------- device scratch (no allocation allowed) --------------------
__device__ float g_feats[BB * EMBED];                    // [256,256]
__device__ float g_base_att[BB * EMBED];                 // feats@W_attFᵀ + b_att
__device__ float g_base_ih[BB * GATES];                  // feats@W_ihFᵀ + b_ih + b_hh
__device__ float g_bsum[GATES];                          // b_ih + b_hh
__device__ float g_ctx[(size_t)BB * TT * EMBED];         // 32 MB
__device__ float g_gin[(size_t)BB * TT * GATES];         // 256 MB  [B,T,2048]
__device__ float g_hs[(size_t)BB * TT * HIDDEN];         // 64 MB   [B,T,512]
__device__ float g_h[BB * HIDDEN];
__device__ float g_c[BB * HIDDEN];
__device__ float g_gates[BB * GATES];                    // per-step h@W_hhᵀ

// -------------------- generic C = A @ Bᵀ (+bias) (+row-broadcast Cadd) --------------------
// A: [M,K] row-major with row stride lda; Bw: [N,K] row-major with row stride ldb.
// Requires: M % BM == 0, K % BK == 0, all row strides % 4 == 0, 16B-aligned pointers.
// N may be arbitrary (guarded).
template <int BM, int BN, int BK, int TM, int TN>
__global__ void gemm_abt(const float* __restrict__ A, int lda,
                         const float* __restrict__ Bw, int ldb,
                         const float* __restrict__ bias,
                         const float* __restrict__ Cadd, int rowdiv,
                         float* __restrict__ C,
                         int M, int N, int K) {
    constexpr int THREADS = (BM / TM) * (BN / TN);
    constexpr int KV = BK / 4;                 // float4 chunks per K-tile row
    constexpr int ROWS_PER_PASS = THREADS / KV;

    __shared__ float As[BK][BM];
    __shared__ float Bs[BK][BN];

    const int tid = threadIdx.x;
    const int block_m = blockIdx.y * BM;
    const int block_n = blockIdx.x * BN;

    const int aRow = tid / KV;
    const int aCol = (tid % KV) * 4;

    const int tcol = tid % (BN / TN);
    const int trow = tid / (BN / TN);

    float acc[TM][TN];
#pragma unroll
    for (int i = 0; i < TM; i++)
#pragma unroll
        for (int j = 0; j < TN; j++) acc[i][j] = 0.f;

    float regM[TM], regN[TN];

    for (int kt = 0; kt < K; kt += BK) {
        // load A tile (transposed into As[k][m])
#pragma unroll
        for (int rr = 0; rr < BM; rr += ROWS_PER_PASS) {
            int r = rr + aRow;
            size_t gidx = (size_t)(block_m + r) * lda + kt + aCol;
            float4 v = *(const float4*)(A + gidx);
            As[aCol + 0][r] = v.x;
            As[aCol + 1][r] = v.y;
            As[aCol + 2][r] = v.z;
            As[aCol + 3][r] = v.w;
        }
        // load B tile (transposed into Bs[k][n]), guard n < N
#pragma unroll
        for (int rr = 0; rr < BN; rr += ROWS_PER_PASS) {
            int r = rr + aRow;
            int gn = block_n + r;
            float4 v = make_float4(0.f, 0.f, 0.f, 0.f);
            if (gn < N) {
                size_t gidx = (size_t)gn * ldb + kt + aCol;
                v = *(const float4*)(Bw + gidx);
            }
            Bs[aCol + 0][r] = v.x;
            Bs[aCol + 1][r] = v.y;
            Bs[aCol + 2][r] = v.z;
            Bs[aCol + 3][r] = v.w;
        }
        __syncthreads();

#pragma unroll
        for (int k = 0; k < BK; k++) {
#pragma unroll
            for (int i = 0; i < TM; i++) regM[i] = As[k][trow * TM + i];
#pragma unroll
            for (int j = 0; j < TN; j++) regN[j] = Bs[k][tcol * TN + j];
#pragma unroll
            for (int i = 0; i < TM; i++)
#pragma unroll
                for (int j = 0; j < TN; j++) acc[i][j] += regM[i] * regN[j];
        }
        __syncthreads();
    }

    // epilogue
#pragma unroll
    for (int i = 0; i < TM; i++) {
        int gm = block_m + trow * TM + i;
        const float* caddrow = nullptr;
        if (Cadd) caddrow = Cadd + (size_t)(rowdiv > 1 ? gm / rowdiv : gm) * N;
#pragma unroll
        for (int j = 0; j < TN; j++) {
            int gn = block_n + tcol * TN + j;
            if (gn < N) {
                float v = acc[i][j];
                if (bias) v += bias[gn];
                if (caddrow) v += caddrow[gn];
                C[(size_t)gm * N + gn] = v;
            }
        }
    }
}

// -------------------- small elementwise kernels --------------------
__global__ void bias_sum_kernel(const float* __restrict__ b_ih,
                                const float* __restrict__ b_hh,
                                float* __restrict__ bsum) {
    int n = blockIdx.x * blockDim.x + threadIdx.x;
    if (n < GATES) bsum[n] = b_ih[n] + b_hh[n];
}

__device__ __forceinline__ float sigmoidf_(float x) {
    return 1.f / (1.f + expf(-x));
}

// gates_total = gatesHH (h@W_hhᵀ, zero at t=0) + gin[:, t, :]; apply LSTM cell.
__global__ void lstm_cell_kernel(const float* __restrict__ gatesHH,
                                 const float* __restrict__ gin,
                                 float* __restrict__ h,
                                 float* __restrict__ c,
                                 float* __restrict__ hs,
                                 int t) {
    int idx = blockIdx.x * blockDim.x + threadIdx.x;  // 0 .. B*HIDDEN-1
    if (idx >= BB * HIDDEN) return;
    int b = idx / HIDDEN;
    int j = idx - b * HIDDEN;

    const float* grow = gin + ((size_t)b * TT + t) * GATES;
    float i_, f_, g_, o_;
    if (t == 0) {
        i_ = grow[j];
        f_ = grow[HIDDEN + j];
        g_ = grow[2 * HIDDEN + j];
        o_ = grow[3 * HIDDEN + j];
    } else {
        const float* ghh = gatesHH + (size_t)b * GATES;
        i_ = ghh[j] + grow[j];
        f_ = ghh[HIDDEN + j] + grow[HIDDEN + j];
        g_ = ghh[2 * HIDDEN + j] + grow[2 * HIDDEN + j];
        o_ = ghh[3 * HIDDEN + j] + grow[3 * HIDDEN + j];
    }

    float cprev = (t == 0) ? 0.f : c[idx];
    float cc = sigmoidf_(f_) * cprev + sigmoidf_(i_) * tanhf(g_);
    float hh = sigmoidf_(o_) * tanhf(cc);
    c[idx] = cc;
    h[idx] = hh;
    hs[((size_t)b * TT + t) * HIDDEN + j] = hh;
}

// -------------------- launch --------------------
extern "C" void kernel_launch(void* const* d_in, const int* in_sizes, int n_in,
                              void* d_out, int out_size) {
    const float* images   = (const float*)d_in[0];   // [256, 2048]
    const float* captions = (const float*)d_in[1];   // [256, 128, 512]
    const float* W_fc     = (const float*)d_in[2];   // [256, 2048]
    const float* b_fc     = (const float*)d_in[3];   // [256]
    const float* W_att    = (const float*)d_in[4];   // [256, 768]
    const float* b_att    = (const float*)d_in[5];   // [256]
    const float* W_ih     = (const float*)d_in[6];   // [2048, 512]
    const float* b_ih     = (const float*)d_in[7];   // [2048]
    const float* W_hh     = (const float*)d_in[8];   // [2048, 512]
    const float* b_hh     = (const float*)d_in[9];   // [2048]
    const float* W_out    = (const float*)d_in[10];  // [1004, 512]
    const float* b_out    = (const float*)d_in[11];  // [1004]
    float* out = (float*)d_out;                      // [256, 128, 1004]

    static float *p_feats = nullptr, *p_batt = nullptr, *p_bih = nullptr,
                 *p_bsum = nullptr, *p_ctx = nullptr, *p_gin = nullptr,
                 *p_hs = nullptr, *p_h = nullptr, *p_c = nullptr, *p_gates = nullptr;
    if (!p_feats) {
        cudaGetSymbolAddress((void**)&p_feats, g_feats);
        cudaGetSymbolAddress((void**)&p_batt, g_base_att);
        cudaGetSymbolAddress((void**)&p_bih, g_base_ih);
        cudaGetSymbolAddress((void**)&p_bsum, g_bsum);
        cudaGetSymbolAddress((void**)&p_ctx, g_ctx);
        cudaGetSymbolAddress((void**)&p_gin, g_gin);
        cudaGetSymbolAddress((void**)&p_hs, g_hs);
        cudaGetSymbolAddress((void**)&p_h, g_h);
        cudaGetSymbolAddress((void**)&p_c, g_c);
        cudaGetSymbolAddress((void**)&p_gates, g_gates);
    }

    auto big = [&](const float* A, int lda, const float* Bw, int ldb,
                   const float* bias, const float* Cadd, int rowdiv,
                   float* C, int M, int N, int K) {
        dim3 grid((N + 127) / 128, M / 128);
        gemm_abt<128, 128, 16, 8, 8><<<grid, 256>>>(A, lda, Bw, ldb, bias, Cadd,
                                                    rowdiv, C, M, N, K);
    };
    auto small = [&](const float* A, int lda, const float* Bw, int ldb,
                     const float* bias, const float* Cadd, int rowdiv,
                     float* C, int M, int N, int K) {
        dim3 grid((N + 63) / 64, M / 64);
        gemm_abt<64, 64, 16, 4, 4><<<grid, 256>>>(A, lda, Bw, ldb, bias, Cadd,
                                                  rowdiv, C, M, N, K);
    };

    // b_ih + b_hh
    bias_sum_kernel<<<(GATES + 255) / 256, 256>>>(b_ih, b_hh, p_bsum);

    // feats = images @ W_fcᵀ + b_fc                [256,256] K=2048
    big(images, FC_IN, W_fc, FC_IN, b_fc, nullptr, 0, p_feats, BB, EMBED, FC_IN);

    // base_att = feats @ W_att[:, :256]ᵀ + b_att   [256,256] K=256
    small(p_feats, EMBED, W_att, HIDDEN + EMBED, b_att, nullptr, 0,
          p_batt, BB, EMBED, EMBED);

    // base_ih = feats @ W_ih[:, :256]ᵀ + (b_ih+b_hh)  [256,2048] K=256
    small(p_feats, EMBED, W_ih, 2 * EMBED, p_bsum, nullptr, 0,
          p_bih, BB, GATES, EMBED);

    // ctx[b*T+t] = captions[b,t] @ W_att[:, 256:]ᵀ + base_att[b]   [32768,256] K=512
    big(captions, HIDDEN, W_att + EMBED, HIDDEN + EMBED, nullptr, p_batt, TT,
        p_ctx, BB * TT, EMBED, HIDDEN);

    // gin[b*T+t] = ctx[b*T+t] @ W_ih[:, 256:]ᵀ + base_ih[b]        [32768,2048] K=256
    big(p_ctx, EMBED, W_ih + EMBED, 2 * EMBED, nullptr, p_bih, TT,
        p_gin, BB * TT, GATES, EMBED);

    // recurrence
    for (int t = 0; t < TT; t++) {
        if (t > 0) {
            // gatesHH = h @ W_hhᵀ    [256,2048] K=512
            small(p_h, HIDDEN, W_hh, HIDDEN, nullptr, nullptr, 0,
                  p_gates, BB, GATES, HIDDEN);
        }
        lstm_cell_kernel<<<(BB * HIDDEN + 255) / 256, 256>>>(
            p_gates, p_gin, p_h, p_c, p_hs, t);
    }

    // out = hs @ W_outᵀ + b_out     [32768,1004] K=512
    big(p_hs, HIDDEN, W_out, HIDDEN, b_out, nullptr, 0,
        out, BB * TT, VOCAB, HIDDEN);
}